// round 15
// baseline (speedup 1.0000x reference)
#include <cuda_runtime.h>
#include <math.h>

#define GRID  592            /* 148 SMs x 4 CTAs: one exact wave at occ 4 */
#define TPB   256
#define NB_N  472            /* NLL blocks; W1 next 60; W2 last 60 */
#define NB_W1 60
#define SGRP  512            /* v8 groups per label stage: 512*32B = 16 KB */

#define FIX_SCALE 268435456.0   /* 2^28 fixed-point scale */

__device__ unsigned long long g_sum_nll = 0;  // signed fixed-point, 2's complement
__device__ unsigned long long g_sum_w1  = 0;
__device__ unsigned long long g_sum_w2  = 0;
__device__ unsigned int g_count = 0;          // atomicInc wraps to 0 each launch

// ---- bulk-async helpers ----
static __device__ __forceinline__ unsigned smem_u32(const void* p) {
    unsigned a;
    asm("{ .reg .u64 t; cvta.to.shared.u64 t, %1; cvt.u32.u64 %0, t; }"
        : "=r"(a) : "l"(p));
    return a;
}
static __device__ __forceinline__ void mbar_init(unsigned mb, unsigned cnt) {
    asm volatile("mbarrier.init.shared::cta.b64 [%0], %1;" :: "r"(mb), "r"(cnt) : "memory");
}
static __device__ __forceinline__ void mbar_expect(unsigned mb, unsigned bytes) {
    asm volatile("mbarrier.arrive.expect_tx.shared::cta.b64 _, [%0], %1;"
                 :: "r"(mb), "r"(bytes) : "memory");
}
static __device__ __forceinline__ void bulk_g2s(unsigned dst, const void* src,
                                                unsigned bytes, unsigned mb) {
    asm volatile("cp.async.bulk.shared::cta.global.mbarrier::complete_tx::bytes "
                 "[%0], [%1], %2, [%3];"
                 :: "r"(dst), "l"(src), "r"(bytes), "r"(mb) : "memory");
}
static __device__ __forceinline__ void mbar_wait(unsigned mb, unsigned ph) {
    asm volatile(
        "{\n\t.reg .pred P;\n\t"
        "LAB%=:\n\t"
        "mbarrier.try_wait.parity.acquire.cta.shared::cta.b64 P, [%0], %1, 0x989680;\n\t"
        "@!P bra LAB%=;\n\t}"
        :: "r"(mb), "r"(ph) : "memory");
}

// ---- 256-bit global loads (sm_100+) ----
static __device__ __forceinline__ void ldg256_f(const float* p, float* r) {
    asm("ld.global.nc.v8.f32 {%0,%1,%2,%3,%4,%5,%6,%7}, [%8];"
        : "=f"(r[0]), "=f"(r[1]), "=f"(r[2]), "=f"(r[3]),
          "=f"(r[4]), "=f"(r[5]), "=f"(r[6]), "=f"(r[7])
        : "l"(p));
}

// log2(picked): picked = label ? p : 1-p, clamped at 1e-8.
static __device__ __forceinline__ float pick_lg2(float p, unsigned int l) {
    float g = __uint_as_float(l * 0x40800000u + 0xBF800000u);  // l? +0.0f : -1.0f
    float pick = fmaxf(fabsf(p + g), 1e-8f);
    return __log2f(pick);
}
static __device__ __forceinline__ float warp_red(float v) {
    #pragma unroll
    for (int o = 16; o; o >>= 1) v += __shfl_down_sync(0xFFFFFFFFu, v, o);
    return v;
}

extern "C" __global__ void __launch_bounds__(TPB, 4)
fused_kernel(const float*    __restrict__ pf,
             const unsigned* __restrict__ lu,
             const float*    __restrict__ w1f,
             const float*    __restrict__ w2f,
             float* __restrict__ out,
             int nq8, int nw18, int nw28,
             int chunk_n, int chunk_w1, int chunk_w2, double invN) {
    __shared__ __align__(128) uint4 lbuf[2][SGRP * 2];   // 2 x 16 KB label stages
    __shared__ __align__(8) unsigned long long smbar[2];

    const int bid = blockIdx.x;
    const int tid = threadIdx.x;

    float accL = 0.0f, a1 = 0.0f, a2 = 0.0f;

    if (bid < NB_N) {
        // ---- NLL: probs via LDG.256, labels via bulk-async double buffer ----
        unsigned mb0 = smem_u32(&smbar[0]);
        unsigned mb1 = smem_u32(&smbar[1]);
        if (tid == 0) {
            mbar_init(mb0, 1);
            mbar_init(mb1, 1);
            asm volatile("fence.proxy.async.shared::cta;" ::: "memory");
        }
        __syncthreads();

        const int gbase = bid * chunk_n;
        const int gend  = min(nq8, gbase + chunk_n);
        const int T     = gend - gbase;
        const int nst   = (T + SGRP - 1) / SGRP;

        if (tid == 0) {
            #pragma unroll
            for (int k = 0; k < 2; k++) {
                if (k < nst) {
                    int cnt = min(SGRP, T - k * SGRP);
                    unsigned mb = k ? mb1 : mb0;
                    mbar_expect(mb, (unsigned)(cnt * 32));
                    bulk_g2s(smem_u32(&lbuf[k][0]),
                             lu + (size_t)(gbase + k * SGRP) * 8,
                             (unsigned)(cnt * 32), mb);
                }
            }
        }

        float acc0 = 0.0f, acc1 = 0.0f;
        for (int s = 0; s < nst; s++) {
            const int b  = s & 1;
            const unsigned mb = b ? mb1 : mb0;
            mbar_wait(mb, (unsigned)((s >> 1) & 1));
            const int cnt = min(SGRP, T - s * SGRP);
            const int g0  = gbase + s * SGRP;

            if (tid < cnt) {
                float p[8];
                ldg256_f(pf + (size_t)(g0 + tid) * 8, p);
                uint4 lA = lbuf[b][2 * tid];
                uint4 lB = lbuf[b][2 * tid + 1];
                acc0 += (pick_lg2(p[0], lA.x) + pick_lg2(p[1], lA.y))
                      + (pick_lg2(p[2], lA.z) + pick_lg2(p[3], lA.w));
                acc0 += (pick_lg2(p[4], lB.x) + pick_lg2(p[5], lB.y))
                      + (pick_lg2(p[6], lB.z) + pick_lg2(p[7], lB.w));
            }
            if (tid + TPB < cnt) {
                float p[8];
                ldg256_f(pf + (size_t)(g0 + TPB + tid) * 8, p);
                uint4 lA = lbuf[b][2 * (TPB + tid)];
                uint4 lB = lbuf[b][2 * (TPB + tid) + 1];
                acc1 += (pick_lg2(p[0], lA.x) + pick_lg2(p[1], lA.y))
                      + (pick_lg2(p[2], lA.z) + pick_lg2(p[3], lA.w));
                acc1 += (pick_lg2(p[4], lB.x) + pick_lg2(p[5], lB.y))
                      + (pick_lg2(p[6], lB.z) + pick_lg2(p[7], lB.w));
            }
            __syncthreads();   // stage buffer fully consumed
            const int sn = s + 2;
            if (tid == 0 && sn < nst) {
                int cn = min(SGRP, T - sn * SGRP);
                mbar_expect(mb, (unsigned)(cn * 32));
                bulk_g2s(smem_u32(&lbuf[b][0]),
                         lu + (size_t)(gbase + sn * SGRP) * 8,
                         (unsigned)(cn * 32), mb);
            }
        }
        accL = acc0 + acc1;   // sum of log2(picked)
    } else {
        // ---- W sum-of-squares: v8 LDG, unroll x2 (R13 path) ----
        const bool isW1 = (bid < NB_N + NB_W1);
        const float* w  = isW1 ? w1f : w2f;
        const int bb    = isW1 ? (bid - NB_N) : (bid - NB_N - NB_W1);
        const int ch    = isW1 ? chunk_w1 : chunk_w2;
        const int nw    = isW1 ? nw18 : nw28;
        const int base  = bb * ch;
        const int end   = min(nw, base + ch);
        float s0 = 0.0f, s1 = 0.0f;
        int i = base + tid;
        for (; i + TPB < end; i += 2 * TPB) {
            float va[8], vb[8];
            ldg256_f(w + (size_t)i * 8, va);
            ldg256_f(w + (size_t)(i + TPB) * 8, vb);
            #pragma unroll
            for (int k = 0; k < 8; k++) s0 = fmaf(va[k], va[k], s0);
            #pragma unroll
            for (int k = 0; k < 8; k++) s1 = fmaf(vb[k], vb[k], s1);
        }
        if (i < end) {
            float va[8];
            ldg256_f(w + (size_t)i * 8, va);
            #pragma unroll
            for (int k = 0; k < 8; k++) s0 = fmaf(va[k], va[k], s0);
        }
        float sw = s0 + s1;
        if (isW1) a1 = sw; else a2 = sw;
    }

    // ---- Block reduction + deterministic fixed-point atomic finish ----
    __shared__ float shL[8], sh1[8], sh2[8];
    const int lane = tid & 31;
    const int wrp  = tid >> 5;
    accL = warp_red(accL);
    a1   = warp_red(a1);
    a2   = warp_red(a2);
    if (lane == 0) { shL[wrp] = accL; sh1[wrp] = a1; sh2[wrp] = a2; }
    __syncthreads();
    if (tid == 0) {
        float vL = 0.0f, v1 = 0.0f, v2 = 0.0f;
        #pragma unroll
        for (int k = 0; k < 8; k++) { vL += shL[k]; v1 += sh1[k]; v2 += sh2[k]; }

        long long fL = llrint((double)vL * FIX_SCALE);
        long long f1 = llrint((double)v1 * FIX_SCALE);
        long long f2 = llrint((double)v2 * FIX_SCALE);
        atomicAdd(&g_sum_nll, (unsigned long long)fL);
        atomicAdd(&g_sum_w1,  (unsigned long long)f1);
        atomicAdd(&g_sum_w2,  (unsigned long long)f2);
        __threadfence();
        unsigned int old = atomicInc(&g_count, GRID - 1);
        if (old == GRID - 1) {
            __threadfence();
            long long tL = (long long)atomicAdd(&g_sum_nll, 0ULL);
            long long t1 = (long long)atomicAdd(&g_sum_w1, 0ULL);
            long long t2 = (long long)atomicAdd(&g_sum_w2, 0ULL);
            double sL = (double)tL / FIX_SCALE;
            double s1 = (double)t1 / FIX_SCALE;
            double s2 = (double)t2 / FIX_SCALE;
            double nll = -sL * 0.6931471805599453 * invN;   // log2 -> ln
            double reg = 0.002 * (sqrt(s1) + sqrt(s2));
            out[0] = (float)(nll + reg);
            g_sum_nll = 0ULL;
            g_sum_w1  = 0ULL;
            g_sum_w2  = 0ULL;
        }
    }
}

extern "C" void kernel_launch(void* const* d_in, const int* in_sizes, int n_in,
                              void* d_out, int out_size) {
    const float*    pf = (const float*)d_in[0];     // output_1: N float32
    const unsigned* lu = (const unsigned*)d_in[1];  // label: N int32
    const float*    w1 = (const float*)d_in[2];
    const float*    w2 = (const float*)d_in[3];
    const int nq8  = in_sizes[0] / 8;   // v8 groups
    const int nw18 = in_sizes[2] / 8;
    const int nw28 = in_sizes[3] / 8;
    const int chunk_n  = (nq8  + NB_N  - 1) / NB_N;
    const int chunk_w1 = (nw18 + NB_W1 - 1) / NB_W1;
    const int nb_w2    = GRID - NB_N - NB_W1;
    const int chunk_w2 = (nw28 + nb_w2 - 1) / nb_w2;
    const double invN = 1.0 / (double)in_sizes[0];

    fused_kernel<<<GRID, TPB>>>(pf, lu, w1, w2, (float*)d_out,
                                nq8, nw18, nw28,
                                chunk_n, chunk_w1, chunk_w2, invN);
}

// round 16
// speedup vs baseline: 1.0601x; 1.0601x over previous
#include <cuda_runtime.h>
#include <math.h>

#define GRID  592            /* 148 SMs x 4 CTAs: one exact wave at occ 4 */
#define TPB   256
#define NB_N  472            /* NLL blocks; W1 next 60; W2 last 60 */
#define NB_W1 60

#define FIX_SCALE 268435456.0   /* 2^28 fixed-point scale */

__device__ unsigned long long g_sum_nll = 0;  // signed fixed-point, 2's complement
__device__ unsigned long long g_sum_w1  = 0;
__device__ unsigned long long g_sum_w2  = 0;
__device__ unsigned int g_count = 0;          // atomicInc wraps to 0 each launch

// 256-bit loads (sm_100+): one LDG.E.256 instead of two LDG.E.128.
static __device__ __forceinline__ void ldg256_f(const float* p, float* r) {
    asm("ld.global.nc.v8.f32 {%0,%1,%2,%3,%4,%5,%6,%7}, [%8];"
        : "=f"(r[0]), "=f"(r[1]), "=f"(r[2]), "=f"(r[3]),
          "=f"(r[4]), "=f"(r[5]), "=f"(r[6]), "=f"(r[7])
        : "l"(p));
}
static __device__ __forceinline__ void ldg256_u(const unsigned* p, unsigned* r) {
    asm("ld.global.nc.v8.b32 {%0,%1,%2,%3,%4,%5,%6,%7}, [%8];"
        : "=r"(r[0]), "=r"(r[1]), "=r"(r[2]), "=r"(r[3]),
          "=r"(r[4]), "=r"(r[5]), "=r"(r[6]), "=r"(r[7])
        : "l"(p));
}

// log2(picked): picked = label ? p : 1-p, clamped at 1e-8.
// x = p + g, g = l ? +0.0f : -1.0f via carry-wrapping IMAD; picked = |x|.
static __device__ __forceinline__ float pick_lg2(float p, unsigned int l) {
    float g = __uint_as_float(l * 0x40800000u + 0xBF800000u);
    float pick = fmaxf(fabsf(p + g), 1e-8f);
    return __log2f(pick);
}
static __device__ __forceinline__ float warp_red(float v) {
    #pragma unroll
    for (int o = 16; o; o >>= 1) v += __shfl_down_sync(0xFFFFFFFFu, v, o);
    return v;
}

extern "C" __global__ void __launch_bounds__(TPB, 4)
fused_kernel(const float*    __restrict__ pf,
             const unsigned* __restrict__ lu,
             const float*    __restrict__ w1f,
             const float*    __restrict__ w2f,
             float* __restrict__ out,
             int nq8, int nw18, int nw28,
             int chunk_n, int chunk_w1, int chunk_w2, double invN) {
    const int bid = blockIdx.x;
    const int tid = threadIdx.x;

    float accL = 0.0f, a1 = 0.0f, a2 = 0.0f;

    if (bid < NB_N) {
        // NLL stream: contiguous chunk of v8 groups, thread-strided.
        const int base = bid * chunk_n;
        const int end  = min(nq8, base + chunk_n);
        float acc0 = 0.0f, acc1 = 0.0f;
        for (int i = base + tid; i < end; i += TPB) {
            float    p[8];
            unsigned l[8];
            ldg256_f(pf + (size_t)i * 8, p);
            ldg256_u(lu + (size_t)i * 8, l);
            acc0 += (pick_lg2(p[0], l[0]) + pick_lg2(p[1], l[1]))
                  + (pick_lg2(p[2], l[2]) + pick_lg2(p[3], l[3]));
            acc1 += (pick_lg2(p[4], l[4]) + pick_lg2(p[5], l[5]))
                  + (pick_lg2(p[6], l[6]) + pick_lg2(p[7], l[7]));
        }
        accL = acc0 + acc1;   // sum of log2(picked)
    } else {
        // W sum-of-squares stream, v8 loads, unroll x2.
        const bool isW1 = (bid < NB_N + NB_W1);
        const float* w  = isW1 ? w1f : w2f;
        const int bb    = isW1 ? (bid - NB_N) : (bid - NB_N - NB_W1);
        const int ch    = isW1 ? chunk_w1 : chunk_w2;
        const int nw    = isW1 ? nw18 : nw28;
        const int base  = bb * ch;
        const int end   = min(nw, base + ch);
        float s0 = 0.0f, s1 = 0.0f;
        int i = base + tid;
        for (; i + TPB < end; i += 2 * TPB) {
            float va[8], vb[8];
            ldg256_f(w + (size_t)i * 8, va);
            ldg256_f(w + (size_t)(i + TPB) * 8, vb);
            #pragma unroll
            for (int k = 0; k < 8; k++) s0 = fmaf(va[k], va[k], s0);
            #pragma unroll
            for (int k = 0; k < 8; k++) s1 = fmaf(vb[k], vb[k], s1);
        }
        if (i < end) {
            float va[8];
            ldg256_f(w + (size_t)i * 8, va);
            #pragma unroll
            for (int k = 0; k < 8; k++) s0 = fmaf(va[k], va[k], s0);
        }
        float sw = s0 + s1;
        if (isW1) a1 = sw; else a2 = sw;
    }

    // Block reduction.
    __shared__ float shL[8], sh1[8], sh2[8];
    const int lane = tid & 31;
    const int wrp  = tid >> 5;
    accL = warp_red(accL);
    a1   = warp_red(a1);
    a2   = warp_red(a2);
    if (lane == 0) { shL[wrp] = accL; sh1[wrp] = a1; sh2[wrp] = a2; }
    __syncthreads();
    if (tid == 0) {
        float vL = 0.0f, v1 = 0.0f, v2 = 0.0f;
        #pragma unroll
        for (int k = 0; k < 8; k++) { vL += shL[k]; v1 += sh1[k]; v2 += sh2[k]; }

        // Deterministic accumulation: signed 2^28 fixed point via u64 atomics
        // (integer add is associative -> order-independent result).
        long long fL = llrint((double)vL * FIX_SCALE);
        long long f1 = llrint((double)v1 * FIX_SCALE);
        long long f2 = llrint((double)v2 * FIX_SCALE);
        atomicAdd(&g_sum_nll, (unsigned long long)fL);
        atomicAdd(&g_sum_w1,  (unsigned long long)f1);
        atomicAdd(&g_sum_w2,  (unsigned long long)f2);
        __threadfence();
        unsigned int old = atomicInc(&g_count, GRID - 1);
        if (old == GRID - 1) {
            // Last arriver: finish and reset totals for the next graph replay.
            __threadfence();
            long long tL = (long long)atomicAdd(&g_sum_nll, 0ULL);
            long long t1 = (long long)atomicAdd(&g_sum_w1, 0ULL);
            long long t2 = (long long)atomicAdd(&g_sum_w2, 0ULL);
            double sL = (double)tL / FIX_SCALE;
            double s1 = (double)t1 / FIX_SCALE;
            double s2 = (double)t2 / FIX_SCALE;
            double nll = -sL * 0.6931471805599453 * invN;   // log2 -> ln
            double reg = 0.002 * (sqrt(s1) + sqrt(s2));
            out[0] = (float)(nll + reg);
            g_sum_nll = 0ULL;
            g_sum_w1  = 0ULL;
            g_sum_w2  = 0ULL;
        }
    }
}

extern "C" void kernel_launch(void* const* d_in, const int* in_sizes, int n_in,
                              void* d_out, int out_size) {
    const float*    pf = (const float*)d_in[0];     // output_1: N float32
    const unsigned* lu = (const unsigned*)d_in[1];  // label: N int32
    const float*    w1 = (const float*)d_in[2];
    const float*    w2 = (const float*)d_in[3];
    const int nq8  = in_sizes[0] / 8;   // v8 groups
    const int nw18 = in_sizes[2] / 8;
    const int nw28 = in_sizes[3] / 8;
    const int chunk_n  = (nq8  + NB_N  - 1) / NB_N;
    const int chunk_w1 = (nw18 + NB_W1 - 1) / NB_W1;
    const int nb_w2    = GRID - NB_N - NB_W1;
    const int chunk_w2 = (nw28 + nb_w2 - 1) / nb_w2;
    const double invN = 1.0 / (double)in_sizes[0];

    fused_kernel<<<GRID, TPB>>>(pf, lu, w1, w2, (float*)d_out,
                                nq8, nw18, nw28,
                                chunk_n, chunk_w1, chunk_w2, invN);
}

// round 17
// speedup vs baseline: 1.0683x; 1.0077x over previous
#include <cuda_runtime.h>
#include <math.h>

#define GRID  888            /* 148 SMs x 6 CTAs: one exact wave at occ 6 */
#define TPB   256
#define NB_N  708            /* NLL blocks; W1 next 90; W2 last 90 */
#define NB_W1 90

#define FIX_SCALE 268435456.0   /* 2^28 fixed-point scale */

__device__ unsigned long long g_sum_nll = 0;  // signed fixed-point, 2's complement
__device__ unsigned long long g_sum_w1  = 0;
__device__ unsigned long long g_sum_w2  = 0;
__device__ unsigned int g_count = 0;          // atomicInc wraps to 0 each launch

// 256-bit loads (sm_100+): one LDG.E.256 instead of two LDG.E.128.
static __device__ __forceinline__ void ldg256_f(const float* p, float* r) {
    asm("ld.global.nc.v8.f32 {%0,%1,%2,%3,%4,%5,%6,%7}, [%8];"
        : "=f"(r[0]), "=f"(r[1]), "=f"(r[2]), "=f"(r[3]),
          "=f"(r[4]), "=f"(r[5]), "=f"(r[6]), "=f"(r[7])
        : "l"(p));
}
static __device__ __forceinline__ void ldg256_u(const unsigned* p, unsigned* r) {
    asm("ld.global.nc.v8.b32 {%0,%1,%2,%3,%4,%5,%6,%7}, [%8];"
        : "=r"(r[0]), "=r"(r[1]), "=r"(r[2]), "=r"(r[3]),
          "=r"(r[4]), "=r"(r[5]), "=r"(r[6]), "=r"(r[7])
        : "l"(p));
}

// log2(picked): picked = label ? p : 1-p, clamped at 1e-8.
// x = p + g, g = l ? +0.0f : -1.0f via carry-wrapping IMAD; picked = |x|.
static __device__ __forceinline__ float pick_lg2(float p, unsigned int l) {
    float g = __uint_as_float(l * 0x40800000u + 0xBF800000u);
    float pick = fmaxf(fabsf(p + g), 1e-8f);
    return __log2f(pick);
}
static __device__ __forceinline__ float warp_red(float v) {
    #pragma unroll
    for (int o = 16; o; o >>= 1) v += __shfl_down_sync(0xFFFFFFFFu, v, o);
    return v;
}

extern "C" __global__ void __launch_bounds__(TPB, 6)
fused_kernel(const float*    __restrict__ pf,
             const unsigned* __restrict__ lu,
             const float*    __restrict__ w1f,
             const float*    __restrict__ w2f,
             float* __restrict__ out,
             int nq8, int nw18, int nw28,
             int chunk_n, int chunk_w1, int chunk_w2, double invN) {
    const int bid = blockIdx.x;
    const int tid = threadIdx.x;

    float accL = 0.0f, a1 = 0.0f, a2 = 0.0f;

    if (bid < NB_N) {
        // NLL stream: contiguous chunk of v8 groups, thread-strided.
        const int base = bid * chunk_n;
        const int end  = min(nq8, base + chunk_n);
        float acc0 = 0.0f, acc1 = 0.0f;
        for (int i = base + tid; i < end; i += TPB) {
            float    p[8];
            unsigned l[8];
            ldg256_f(pf + (size_t)i * 8, p);
            ldg256_u(lu + (size_t)i * 8, l);
            acc0 += (pick_lg2(p[0], l[0]) + pick_lg2(p[1], l[1]))
                  + (pick_lg2(p[2], l[2]) + pick_lg2(p[3], l[3]));
            acc1 += (pick_lg2(p[4], l[4]) + pick_lg2(p[5], l[5]))
                  + (pick_lg2(p[6], l[6]) + pick_lg2(p[7], l[7]));
        }
        accL = acc0 + acc1;   // sum of log2(picked)
    } else {
        // W sum-of-squares stream, v8 loads.
        const bool isW1 = (bid < NB_N + NB_W1);
        const float* w  = isW1 ? w1f : w2f;
        const int bb    = isW1 ? (bid - NB_N) : (bid - NB_N - NB_W1);
        const int ch    = isW1 ? chunk_w1 : chunk_w2;
        const int nw    = isW1 ? nw18 : nw28;
        const int base  = bb * ch;
        const int end   = min(nw, base + ch);
        float s0 = 0.0f, s1 = 0.0f;
        int i = base + tid;
        for (; i + TPB < end; i += 2 * TPB) {
            float va[8], vb[8];
            ldg256_f(w + (size_t)i * 8, va);
            ldg256_f(w + (size_t)(i + TPB) * 8, vb);
            #pragma unroll
            for (int k = 0; k < 8; k++) s0 = fmaf(va[k], va[k], s0);
            #pragma unroll
            for (int k = 0; k < 8; k++) s1 = fmaf(vb[k], vb[k], s1);
        }
        if (i < end) {
            float va[8];
            ldg256_f(w + (size_t)i * 8, va);
            #pragma unroll
            for (int k = 0; k < 8; k++) s0 = fmaf(va[k], va[k], s0);
        }
        float sw = s0 + s1;
        if (isW1) a1 = sw; else a2 = sw;
    }

    // Block reduction.
    __shared__ float shL[8], sh1[8], sh2[8];
    const int lane = tid & 31;
    const int wrp  = tid >> 5;
    accL = warp_red(accL);
    a1   = warp_red(a1);
    a2   = warp_red(a2);
    if (lane == 0) { shL[wrp] = accL; sh1[wrp] = a1; sh2[wrp] = a2; }
    __syncthreads();
    if (tid == 0) {
        float vL = 0.0f, v1 = 0.0f, v2 = 0.0f;
        #pragma unroll
        for (int k = 0; k < 8; k++) { vL += shL[k]; v1 += sh1[k]; v2 += sh2[k]; }

        // Deterministic accumulation: signed 2^28 fixed point via u64 atomics
        // (integer add is associative -> order-independent result).
        long long fL = llrint((double)vL * FIX_SCALE);
        long long f1 = llrint((double)v1 * FIX_SCALE);
        long long f2 = llrint((double)v2 * FIX_SCALE);
        atomicAdd(&g_sum_nll, (unsigned long long)fL);
        atomicAdd(&g_sum_w1,  (unsigned long long)f1);
        atomicAdd(&g_sum_w2,  (unsigned long long)f2);
        __threadfence();
        unsigned int old = atomicInc(&g_count, GRID - 1);
        if (old == GRID - 1) {
            // Last arriver: finish and reset totals for the next graph replay.
            __threadfence();
            long long tL = (long long)atomicAdd(&g_sum_nll, 0ULL);
            long long t1 = (long long)atomicAdd(&g_sum_w1, 0ULL);
            long long t2 = (long long)atomicAdd(&g_sum_w2, 0ULL);
            double sL = (double)tL / FIX_SCALE;
            double s1 = (double)t1 / FIX_SCALE;
            double s2 = (double)t2 / FIX_SCALE;
            double nll = -sL * 0.6931471805599453 * invN;   // log2 -> ln
            double reg = 0.002 * (sqrt(s1) + sqrt(s2));
            out[0] = (float)(nll + reg);
            g_sum_nll = 0ULL;
            g_sum_w1  = 0ULL;
            g_sum_w2  = 0ULL;
        }
    }
}

extern "C" void kernel_launch(void* const* d_in, const int* in_sizes, int n_in,
                              void* d_out, int out_size) {
    const float*    pf = (const float*)d_in[0];     // output_1: N float32
    const unsigned* lu = (const unsigned*)d_in[1];  // label: N int32
    const float*    w1 = (const float*)d_in[2];
    const float*    w2 = (const float*)d_in[3];
    const int nq8  = in_sizes[0] / 8;   // v8 groups
    const int nw18 = in_sizes[2] / 8;
    const int nw28 = in_sizes[3] / 8;
    const int chunk_n  = (nq8  + NB_N  - 1) / NB_N;
    const int chunk_w1 = (nw18 + NB_W1 - 1) / NB_W1;
    const int nb_w2    = GRID - NB_N - NB_W1;
    const int chunk_w2 = (nw28 + nb_w2 - 1) / nb_w2;
    const double invN = 1.0 / (double)in_sizes[0];

    fused_kernel<<<GRID, TPB>>>(pf, lu, w1, w2, (float*)d_out,
                                nq8, nw18, nw28,
                                chunk_n, chunk_w1, chunk_w2, invN);
}